// round 1
// baseline (speedup 1.0000x reference)
#include <cuda_runtime.h>
#include <math.h>

#define N_ 4
#define C_ 128
#define COUT_ 128
#define H_ 96
#define W_ 96
#define HW_ (H_*W_)
#define CK_ 1152          // C*9
#define TILE_ 8           // dcn pixel tile 8x8
#define TPI_ 12           // tiles per image dim (96/8)
#define NTILES_ (TPI_*TPI_) // 144
#define GN_GROUPS_ 8
#define GN_EPS_ 1e-5f
#define CNT_PER_GROUP_ (16.0f*HW_)   // (Cout/G)*H*W = 16*9216

// ---------------- scratch (no allocation allowed) ----------------
__device__ float g_dx[N_*HW_];
__device__ float g_dy[N_*HW_];
__device__ float g_mask[N_*HW_];
__device__ float g_wT[CK_*COUT_];            // [c*9+k][o]
__device__ float g_part[N_*GN_GROUPS_*NTILES_*2]; // per-tile (sum,sumsq)
__device__ float g_stats[N_*GN_GROUPS_*2];   // (mean, rstd)

// ---------------- kernel 1: weight transpose ----------------
__global__ void k_transpose(const float* __restrict__ w_dcn) {
    int i = blockIdx.x * 256 + threadIdx.x;
    if (i < CK_*COUT_) {
        int o = i / CK_;
        int ck = i % CK_;
        g_wT[ck*COUT_ + o] = w_dcn[i];
    }
}

// ---------------- kernel 2: head conv + activations ----------------
// grid: N*36 blocks (16x16 pixel tiles), 256 threads (1 px/thread)
__global__ __launch_bounds__(256) void k_head(const float* __restrict__ x,
                                              const float* __restrict__ w_head,
                                              const float* __restrict__ b_head) {
    __shared__ float whf[3*C_*9];     // [o][c][k]
    __shared__ float win[18*18];

    int tid = threadIdx.x;
    int bx  = blockIdx.x;
    int n   = bx / 36;
    int t   = bx % 36;
    int by0 = (t / 6) * 16;
    int bx0 = (t % 6) * 16;

    for (int i = tid; i < 3*C_*9; i += 256) whf[i] = w_head[i];

    int ly = tid / 16, lx = tid % 16;
    float h0 = 0.f, h1 = 0.f, h2 = 0.f;

    for (int c = 0; c < C_; c++) {
        __syncthreads();
        for (int i = tid; i < 18*18; i += 256) {
            int r = i / 18, cc = i % 18;
            int gy = by0 - 1 + r, gx = bx0 - 1 + cc;
            float v = 0.f;
            if (gy >= 0 && gy < H_ && gx >= 0 && gx < W_)
                v = x[((n*C_ + c)*H_ + gy)*W_ + gx];
            win[i] = v;
        }
        __syncthreads();
        #pragma unroll
        for (int k = 0; k < 9; k++) {
            int ky = k / 3, kx = k % 3;
            float v = win[(ly + ky)*18 + lx + kx];
            h0 += v * whf[(0*C_ + c)*9 + k];
            h1 += v * whf[(1*C_ + c)*9 + k];
            h2 += v * whf[(2*C_ + c)*9 + k];
        }
    }
    h0 += b_head[0]; h1 += b_head[1]; h2 += b_head[2];

    int gy = by0 + ly, gx = bx0 + lx;
    int pix = n*HW_ + gy*W_ + gx;
    g_dx[pix]   = 0.25f * tanhf(h0);
    g_dy[pix]   = 0.25f * tanhf(h1);
    g_mask[pix] = 1.f / (1.f + expf(-h2));
}

// ---------------- kernel 3: deformable sampling + GEMM ----------------
// grid: N*144 blocks (8x8 px tiles), 256 threads: thread=(o=tid&127, pgrp=tid>>7)
__global__ __launch_bounds__(256) void k_dcn(const float* __restrict__ x,
                                             float* __restrict__ out) {
    __shared__ float win[12*12];
    __shared__ __align__(16) float samp[9][64];
    __shared__ short  bidx[64*9];
    __shared__ float4 wgt[64*9];
    __shared__ float red_s[256];
    __shared__ float red_q[256];

    int tid = threadIdx.x;
    int bx  = blockIdx.x;
    int n    = bx / NTILES_;
    int tile = bx % NTILES_;
    int ty0 = (tile / TPI_) * TILE_;
    int tx0 = (tile % TPI_) * TILE_;
    int wy0 = ty0 - 2, wx0 = tx0 - 2;

    // ---- per-block precompute: bilinear corner base + weights (mask folded) ----
    if (tid < 64) {
        int p = tid;
        int ly = p >> 3, lx = p & 7;
        int gy = ty0 + ly, gx = tx0 + lx;
        int pix = n*HW_ + gy*W_ + gx;
        float dx = g_dx[pix], dy = g_dy[pix], m = g_mask[pix];
        const float syc[9] = {0,0,0, 1,0,-1, 1,1,-1};
        const float sxc[9] = {0,1,-1, 0,0,0, 1,-1,1};
        #pragma unroll
        for (int k = 0; k < 9; k++) {
            int ky = k / 3, kx = k % 3;
            float py = (float)(gy + ky - 1) + syc[k]*dx;
            float px = (float)(gx + kx - 1) + sxc[k]*dy;
            float fy0 = floorf(py), fx0 = floorf(px);
            int y0 = (int)fy0, x0 = (int)fx0;
            float fy = py - fy0, fx = px - fx0;
            float v00 = (y0   >= 0 && y0   < H_ && x0   >= 0 && x0   < W_) ? 1.f : 0.f;
            float v01 = (y0   >= 0 && y0   < H_ && x0+1 >= 0 && x0+1 < W_) ? 1.f : 0.f;
            float v10 = (y0+1 >= 0 && y0+1 < H_ && x0   >= 0 && x0   < W_) ? 1.f : 0.f;
            float v11 = (y0+1 >= 0 && y0+1 < H_ && x0+1 >= 0 && x0+1 < W_) ? 1.f : 0.f;
            float4 w4;
            w4.x = (1.f-fy)*(1.f-fx)*v00*m;
            w4.y = (1.f-fy)*fx      *v01*m;
            w4.z = fy      *(1.f-fx)*v10*m;
            w4.w = fy      *fx      *v11*m;
            int ly0 = min(max(y0 - wy0, 0), 10);
            int lx0 = min(max(x0 - wx0, 0), 10);
            bidx[p*9 + k] = (short)(ly0*12 + lx0);
            wgt[p*9 + k]  = w4;
        }
    }

    float acc[32];
    #pragma unroll
    for (int i = 0; i < 32; i++) acc[i] = 0.f;

    int o   = tid & 127;
    int pb  = (tid >> 7) * 32;
    const float* wTo = g_wT + o;

    for (int c = 0; c < C_; c++) {
        __syncthreads();   // protects win + (first iter) precompute tables
        // window load: 12x12 plane slice
        if (tid < 144) {
            int r = tid / 12, cc = tid % 12;
            int gy = wy0 + r, gx = wx0 + cc;
            float v = 0.f;
            if (gy >= 0 && gy < H_ && gx >= 0 && gx < W_)
                v = x[((n*C_ + c)*H_ + gy)*W_ + gx];
            win[tid] = v;
        }
        __syncthreads();
        // sampled[k][p] for this channel
        for (int i = tid; i < 576; i += 256) {
            int k = i >> 6, p = i & 63;
            int base = bidx[p*9 + k];
            float4 w4 = wgt[p*9 + k];
            samp[k][p] = w4.x*win[base]      + w4.y*win[base+1]
                       + w4.z*win[base+12]   + w4.w*win[base+13];
        }
        __syncthreads();
        // accumulate: acc[p] += w[o,c,k] * samp[k][p]
        const float* wrow = wTo + c*9*COUT_;
        #pragma unroll
        for (int k = 0; k < 9; k++) {
            float wv = wrow[k*COUT_];
            const float4* s4 = (const float4*)(&samp[k][pb]);
            #pragma unroll
            for (int j = 0; j < 8; j++) {
                float4 v = s4[j];
                acc[4*j+0] += wv * v.x;
                acc[4*j+1] += wv * v.y;
                acc[4*j+2] += wv * v.z;
                acc[4*j+3] += wv * v.w;
            }
        }
    }

    // ---- write y + deterministic per-block GN partials ----
    float ls = 0.f, lq = 0.f;
    #pragma unroll
    for (int j = 0; j < 32; j++) {
        int p = pb + j;
        int ly = p >> 3, lx = p & 7;
        int gy = ty0 + ly, gx = tx0 + lx;
        float v = acc[j];
        out[((n*COUT_ + o)*H_ + gy)*W_ + gx] = v;
        ls += v; lq += v*v;
    }
    red_s[tid] = ls; red_q[tid] = lq;
    __syncthreads();
    if (tid < 8) {  // tid = group id; sum the 16 o-channels x 2 pixel-groups
        float s = 0.f, q = 0.f;
        #pragma unroll
        for (int grp = 0; grp < 2; grp++)
            for (int j = 0; j < 16; j++) {
                int t = grp*128 + tid*16 + j;
                s += red_s[t]; q += red_q[t];
            }
        int base = (((n*GN_GROUPS_ + tid)*NTILES_) + tile)*2;
        g_part[base + 0] = s;
        g_part[base + 1] = q;
    }
}

// ---------------- kernel 4: GN stats reduce ----------------
__global__ void k_gnreduce() {
    int t = threadIdx.x;
    if (t < N_*GN_GROUPS_) {
        float s = 0.f, q = 0.f;
        for (int i = 0; i < NTILES_; i++) {
            s += g_part[(t*NTILES_ + i)*2 + 0];
            q += g_part[(t*NTILES_ + i)*2 + 1];
        }
        float inv = 1.f / CNT_PER_GROUP_;
        float mean = s * inv;
        float var  = q * inv - mean*mean;
        g_stats[t*2 + 0] = mean;
        g_stats[t*2 + 1] = rsqrtf(var + GN_EPS_);
    }
}

// ---------------- kernel 5: normalize + affine + relu ----------------
__global__ void k_apply(float* __restrict__ out,
                        const float* __restrict__ gamma,
                        const float* __restrict__ beta) {
    int i = blockIdx.x * 256 + threadIdx.x;
    if (i >= N_*COUT_*HW_) return;
    int c = (i / HW_) % COUT_;
    int n = i / (HW_*COUT_);
    int g = c >> 4;
    float mean = g_stats[(n*GN_GROUPS_ + g)*2 + 0];
    float rstd = g_stats[(n*GN_GROUPS_ + g)*2 + 1];
    float v = (out[i] - mean) * rstd * gamma[c] + beta[c];
    out[i] = fmaxf(v, 0.f);
}

extern "C" void kernel_launch(void* const* d_in, const int* in_sizes, int n_in,
                              void* d_out, int out_size) {
    const float* x       = (const float*)d_in[0];
    const float* w_head  = (const float*)d_in[1];
    const float* b_head  = (const float*)d_in[2];
    const float* w_dcn   = (const float*)d_in[3];
    const float* gamma   = (const float*)d_in[4];
    const float* beta    = (const float*)d_in[5];
    float* out = (float*)d_out;

    k_transpose<<<(CK_*COUT_ + 255)/256, 256>>>(w_dcn);
    k_head<<<N_*36, 256>>>(x, w_head, b_head);
    k_dcn<<<N_*NTILES_, 256>>>(x, out);
    k_gnreduce<<<1, 32>>>();
    k_apply<<<(N_*COUT_*HW_ + 255)/256, 256>>>(out, gamma, beta);
}

// round 4
// speedup vs baseline: 1.3707x; 1.3707x over previous
#include <cuda_runtime.h>
#include <math.h>

#define N_ 4
#define C_ 128
#define COUT_ 128
#define H_ 96
#define W_ 96
#define HW_ (H_*W_)
#define CK_ 1152          // C*9
#define TILE_ 8           // dcn pixel tile 8x8
#define TPI_ 12           // tiles per image dim (96/8)
#define NTILES_ (TPI_*TPI_) // 144
#define GN_GROUPS_ 8
#define GN_EPS_ 1e-5f
#define CNT_PER_GROUP_ (16.0f*HW_)   // (Cout/G)*H*W
#define CB_ 4             // channels per dcn main-loop iteration
#define WINSZ_ 144        // 12x12 window

// ---------------- scratch (no allocation allowed) ----------------
__device__ float g_dx[N_*HW_];
__device__ float g_dy[N_*HW_];
__device__ float g_mask[N_*HW_];
__device__ float g_wT[CK_*COUT_];            // [c*9+k][o]
__device__ float g_part[N_*GN_GROUPS_*NTILES_*2]; // per-tile (sum,sumsq)
__device__ float g_stats[N_*GN_GROUPS_*2];   // (mean, rstd)

// ---------------- f32x2 helpers (SASS FFMA2 via PTX) ----------------
__device__ __forceinline__ unsigned long long ffma2(unsigned long long a,
                                                    unsigned long long b,
                                                    unsigned long long c) {
    unsigned long long d;
    asm("fma.rn.f32x2 %0, %1, %2, %3;" : "=l"(d) : "l"(a), "l"(b), "l"(c));
    return d;
}
__device__ __forceinline__ unsigned long long bcast2(float a) {
    unsigned long long r;
    asm("mov.b64 %0, {%1, %1};" : "=l"(r) : "f"(a));
    return r;
}
__device__ __forceinline__ float lo2(unsigned long long v) {
    return __uint_as_float((unsigned int)(v & 0xffffffffull));
}
__device__ __forceinline__ float hi2(unsigned long long v) {
    return __uint_as_float((unsigned int)(v >> 32));
}

// ---------------- kernel 1: weight transpose ----------------
__global__ void k_transpose(const float* __restrict__ w_dcn) {
    int i = blockIdx.x * 256 + threadIdx.x;
    if (i < CK_*COUT_) {
        int o = i / CK_;
        int ck = i % CK_;
        g_wT[ck*COUT_ + o] = w_dcn[i];
    }
}

// ---------------- kernel 2: head conv + activations ----------------
// grid: N*36 blocks (16x16 pixel tiles), 256 threads (1 px/thread), 2 ch/iter
__global__ __launch_bounds__(256) void k_head(const float* __restrict__ x,
                                              const float* __restrict__ w_head,
                                              const float* __restrict__ b_head) {
    __shared__ float whf[3*C_*9];     // [o][c][k]
    __shared__ float win[2*18*18];

    int tid = threadIdx.x;
    int bx  = blockIdx.x;
    int n   = bx / 36;
    int t   = bx % 36;
    int by0 = (t / 6) * 16;
    int bx0 = (t % 6) * 16;

    for (int i = tid; i < 3*C_*9; i += 256) whf[i] = w_head[i];

    int ly = tid / 16, lx = tid % 16;
    float h0 = 0.f, h1 = 0.f, h2 = 0.f;

    for (int c0 = 0; c0 < C_; c0 += 2) {
        __syncthreads();
        for (int i = tid; i < 2*18*18; i += 256) {
            int cb = i / 324;
            int r  = (i % 324) / 18, cc = (i % 324) % 18;
            int gy = by0 - 1 + r, gx = bx0 - 1 + cc;
            float v = 0.f;
            if (gy >= 0 && gy < H_ && gx >= 0 && gx < W_)
                v = x[((n*C_ + c0 + cb)*H_ + gy)*W_ + gx];
            win[i] = v;
        }
        __syncthreads();
        #pragma unroll
        for (int cb = 0; cb < 2; cb++) {
            int c = c0 + cb;
            #pragma unroll
            for (int k = 0; k < 9; k++) {
                int ky = k / 3, kx = k % 3;
                float v = win[cb*324 + (ly + ky)*18 + lx + kx];
                h0 += v * whf[(0*C_ + c)*9 + k];
                h1 += v * whf[(1*C_ + c)*9 + k];
                h2 += v * whf[(2*C_ + c)*9 + k];
            }
        }
    }
    h0 += b_head[0]; h1 += b_head[1]; h2 += b_head[2];

    int gy = by0 + ly, gx = bx0 + lx;
    int pix = n*HW_ + gy*W_ + gx;
    g_dx[pix]   = 0.25f * tanhf(h0);
    g_dy[pix]   = 0.25f * tanhf(h1);
    g_mask[pix] = 1.f / (1.f + expf(-h2));
}

// ---------------- kernel 3: deformable sampling + GEMM ----------------
// grid: N*144 blocks (8x8 px tiles), 256 threads: thread=(o=tid&127, pgrp=tid>>7)
// Inner GEMM uses packed f32x2 FFMA2 on pixel pairs.
__global__ __launch_bounds__(256, 2) void k_dcn(const float* __restrict__ x,
                                                float* __restrict__ out) {
    __shared__ float win[CB_*WINSZ_];
    __shared__ __align__(16) float samp[CB_][9][64];
    __shared__ short  bidx[9*64];        // [k][p]
    __shared__ __align__(16) float4 wgt[9*64];  // [k][p]
    __shared__ float red_s[256];
    __shared__ float red_q[256];

    int tid = threadIdx.x;
    int bx  = blockIdx.x;
    int n    = bx / NTILES_;
    int tile = bx % NTILES_;
    int ty0 = (tile / TPI_) * TILE_;
    int tx0 = (tile % TPI_) * TILE_;
    int wy0 = ty0 - 2, wx0 = tx0 - 2;

    // ---- per-block precompute: bilinear corner base + weights (mask folded) ----
    if (tid < 64) {
        int p = tid;
        int ly = p >> 3, lx = p & 7;
        int gy = ty0 + ly, gx = tx0 + lx;
        int pix = n*HW_ + gy*W_ + gx;
        float dx = g_dx[pix], dy = g_dy[pix], m = g_mask[pix];
        const float syc[9] = {0,0,0, 1,0,-1, 1,1,-1};
        const float sxc[9] = {0,1,-1, 0,0,0, 1,-1,1};
        #pragma unroll
        for (int k = 0; k < 9; k++) {
            int ky = k / 3, kx = k % 3;
            float py = (float)(gy + ky - 1) + syc[k]*dx;
            float px = (float)(gx + kx - 1) + sxc[k]*dy;
            float fy0 = floorf(py), fx0 = floorf(px);
            int y0 = (int)fy0, x0 = (int)fx0;
            float fy = py - fy0, fx = px - fx0;
            float v00 = (y0   >= 0 && y0   < H_ && x0   >= 0 && x0   < W_) ? 1.f : 0.f;
            float v01 = (y0   >= 0 && y0   < H_ && x0+1 >= 0 && x0+1 < W_) ? 1.f : 0.f;
            float v10 = (y0+1 >= 0 && y0+1 < H_ && x0   >= 0 && x0   < W_) ? 1.f : 0.f;
            float v11 = (y0+1 >= 0 && y0+1 < H_ && x0+1 >= 0 && x0+1 < W_) ? 1.f : 0.f;
            float4 w4;
            w4.x = (1.f-fy)*(1.f-fx)*v00*m;
            w4.y = (1.f-fy)*fx      *v01*m;
            w4.z = fy      *(1.f-fx)*v10*m;
            w4.w = fy      *fx      *v11*m;
            int ly0 = min(max(y0 - wy0, 0), 10);
            int lx0 = min(max(x0 - wx0, 0), 10);
            bidx[k*64 + p] = (short)(ly0*12 + lx0);
            wgt[k*64 + p]  = w4;
        }
    }

    unsigned long long acc2[16];
    #pragma unroll
    for (int i = 0; i < 16; i++) acc2[i] = 0ull;

    int o   = tid & 127;
    int pb  = (tid >> 7) * 32;
    const float* wTo = g_wT + o;

    int sp = tid & 63;           // sampling: pixel
    int scb = tid >> 6;          // sampling: channel within batch

    for (int c0 = 0; c0 < C_; c0 += CB_) {
        // --- preload weights for CB channels (latency overlaps barriers/sampling)
        float wv[CB_*9];
        const float* wbase = wTo + (c0*9)*COUT_;
        #pragma unroll
        for (int u = 0; u < CB_*9; u++) wv[u] = wbase[u*COUT_];

        __syncthreads();   // prev GEMM done reading samp; win free; (iter0: precompute visible)
        // --- window load: CB 12x12 planes
        #pragma unroll
        for (int i = tid; i < CB_*WINSZ_; i += 256) {
            int cb = i / WINSZ_;
            int r  = (i % WINSZ_) / 12, cc = (i % WINSZ_) % 12;
            int gy = wy0 + r, gx = wx0 + cc;
            float v = 0.f;
            if (gy >= 0 && gy < H_ && gx >= 0 && gx < W_)
                v = x[((n*C_ + c0 + cb)*H_ + gy)*W_ + gx];
            win[i] = v;
        }
        __syncthreads();
        // --- sampling: each thread one (cb, p), loop k
        {
            const float* wp = &win[scb*WINSZ_];
            #pragma unroll
            for (int k = 0; k < 9; k++) {
                int base = bidx[k*64 + sp];
                float4 w4 = wgt[k*64 + sp];
                samp[scb][k][sp] = w4.x*wp[base]    + w4.y*wp[base+1]
                                 + w4.z*wp[base+12] + w4.w*wp[base+13];
            }
        }
        __syncthreads();
        // --- GEMM: acc[p] += w[o,c,k] * samp[cb][k][p], packed pixel pairs
        #pragma unroll
        for (int cb = 0; cb < CB_; cb++) {
            #pragma unroll
            for (int k = 0; k < 9; k++) {
                unsigned long long wv2 = bcast2(wv[cb*9 + k]);
                const ulonglong2* s2 = (const ulonglong2*)(&samp[cb][k][pb]);
                #pragma unroll
                for (int j = 0; j < 8; j++) {
                    ulonglong2 v = s2[j];
                    acc2[2*j]   = ffma2(wv2, v.x, acc2[2*j]);
                    acc2[2*j+1] = ffma2(wv2, v.y, acc2[2*j+1]);
                }
            }
        }
    }

    // ---- write y + deterministic per-block GN partials ----
    float ls = 0.f, lq = 0.f;
    #pragma unroll
    for (int i = 0; i < 16; i++) {
        float a = lo2(acc2[i]);
        float b = hi2(acc2[i]);
        int p0 = pb + 2*i;
        int ly = p0 >> 3, lx = p0 & 7;      // p0 even -> same row as p0+1
        int gy = ty0 + ly, gx = tx0 + lx;
        long idx = ((long)(n*COUT_ + o)*H_ + gy)*W_ + gx;
        out[idx]     = a;
        out[idx + 1] = b;
        ls += a + b; lq += a*a + b*b;
    }
    red_s[tid] = ls; red_q[tid] = lq;
    __syncthreads();
    if (tid < 8) {  // tid = group id; sum the 16 o-channels x 2 pixel-groups
        float s = 0.f, q = 0.f;
        #pragma unroll
        for (int grp = 0; grp < 2; grp++)
            for (int j = 0; j < 16; j++) {
                int t = grp*128 + tid*16 + j;
                s += red_s[t]; q += red_q[t];
            }
        int base = (((n*GN_GROUPS_ + tid)*NTILES_) + tile)*2;
        g_part[base + 0] = s;
        g_part[base + 1] = q;
    }
}

// ---------------- kernel 4: GN stats reduce ----------------
__global__ void k_gnreduce() {
    int t = threadIdx.x;
    if (t < N_*GN_GROUPS_) {
        float s = 0.f, q = 0.f;
        for (int i = 0; i < NTILES_; i++) {
            s += g_part[(t*NTILES_ + i)*2 + 0];
            q += g_part[(t*NTILES_ + i)*2 + 1];
        }
        float inv = 1.f / CNT_PER_GROUP_;
        float mean = s * inv;
        float var  = q * inv - mean*mean;
        g_stats[t*2 + 0] = mean;
        g_stats[t*2 + 1] = rsqrtf(var + GN_EPS_);
    }
}

// ---------------- kernel 5: normalize + affine + relu ----------------
__global__ void k_apply(float* __restrict__ out,
                        const float* __restrict__ gamma,
                        const float* __restrict__ beta) {
    int i = blockIdx.x * 256 + threadIdx.x;
    if (i >= N_*COUT_*HW_) return;
    int c = (i / HW_) % COUT_;
    int n = i / (HW_*COUT_);
    int g = c >> 4;
    float mean = g_stats[(n*GN_GROUPS_ + g)*2 + 0];
    float rstd = g_stats[(n*GN_GROUPS_ + g)*2 + 1];
    float v = (out[i] - mean) * rstd * gamma[c] + beta[c];
    out[i] = fmaxf(v, 0.f);
}

extern "C" void kernel_launch(void* const* d_in, const int* in_sizes, int n_in,
                              void* d_out, int out_size) {
    const float* x       = (const float*)d_in[0];
    const float* w_head  = (const float*)d_in[1];
    const float* b_head  = (const float*)d_in[2];
    const float* w_dcn   = (const float*)d_in[3];
    const float* gamma   = (const float*)d_in[4];
    const float* beta    = (const float*)d_in[5];
    float* out = (float*)d_out;

    k_transpose<<<(CK_*COUT_ + 255)/256, 256>>>(w_dcn);
    k_head<<<N_*36, 256>>>(x, w_head, b_head);
    k_dcn<<<N_*NTILES_, 256>>>(x, out);
    k_gnreduce<<<1, 32>>>();
    k_apply<<<(N_*COUT_*HW_ + 255)/256, 256>>>(out, gamma, beta);
}

// round 5
// speedup vs baseline: 1.3720x; 1.0009x over previous
#include <cuda_runtime.h>
#include <math.h>

#define N_ 4
#define C_ 128
#define COUT_ 128
#define H_ 96
#define W_ 96
#define HW_ (H_*W_)
#define CK_ 1152          // C*9
#define TILE_ 8           // dcn pixel tile 8x8
#define TPI_ 12           // tiles per image dim (96/8)
#define NTILES_ (TPI_*TPI_) // 144
#define GN_GROUPS_ 8
#define GN_EPS_ 1e-5f
#define CNT_PER_GROUP_ (16.0f*HW_)   // (Cout/G)*H*W
#define CB_ 4             // channels per dcn main-loop iteration
#define WINSZ_ 144        // 12x12 window

// ---------------- scratch (no allocation allowed) ----------------
__device__ float g_dx[N_*HW_];
__device__ float g_dy[N_*HW_];
__device__ float g_mask[N_*HW_];
__device__ float g_wT[CK_*COUT_];            // [c*9+k][o]
__device__ float g_part[N_*GN_GROUPS_*NTILES_*2]; // per-tile (sum,sumsq)
__device__ float g_stats[N_*GN_GROUPS_*2];   // (mean, rstd)

// ---------------- f32x2 helpers (SASS FFMA2 via PTX) ----------------
__device__ __forceinline__ unsigned long long ffma2(unsigned long long a,
                                                    unsigned long long b,
                                                    unsigned long long c) {
    unsigned long long d;
    asm("fma.rn.f32x2 %0, %1, %2, %3;" : "=l"(d) : "l"(a), "l"(b), "l"(c));
    return d;
}
__device__ __forceinline__ unsigned long long bcast2(float a) {
    unsigned long long r;
    asm("mov.b64 %0, {%1, %1};" : "=l"(r) : "f"(a));
    return r;
}
__device__ __forceinline__ float lo2(unsigned long long v) {
    return __uint_as_float((unsigned int)(v & 0xffffffffull));
}
__device__ __forceinline__ float hi2(unsigned long long v) {
    return __uint_as_float((unsigned int)(v >> 32));
}

// ---------------- kernel 1: weight transpose ----------------
__global__ void k_transpose(const float* __restrict__ w_dcn) {
    int i = blockIdx.x * 256 + threadIdx.x;
    if (i < CK_*COUT_) {
        int o = i / CK_;
        int ck = i % CK_;
        g_wT[ck*COUT_ + o] = w_dcn[i];
    }
}

// ---------------- kernel 2: head conv + activations ----------------
// grid: N*36 blocks (16x16 pixel tiles), 256 threads (1 px/thread), 2 ch/iter
__global__ __launch_bounds__(256) void k_head(const float* __restrict__ x,
                                              const float* __restrict__ w_head,
                                              const float* __restrict__ b_head) {
    __shared__ float whf[3*C_*9];     // [o][c][k]
    __shared__ float win[2*18*18];

    int tid = threadIdx.x;
    int bx  = blockIdx.x;
    int n   = bx / 36;
    int t   = bx % 36;
    int by0 = (t / 6) * 16;
    int bx0 = (t % 6) * 16;

    for (int i = tid; i < 3*C_*9; i += 256) whf[i] = w_head[i];

    int ly = tid / 16, lx = tid % 16;
    float h0 = 0.f, h1 = 0.f, h2 = 0.f;

    for (int c0 = 0; c0 < C_; c0 += 2) {
        __syncthreads();
        for (int i = tid; i < 2*18*18; i += 256) {
            int cb = i / 324;
            int r  = (i % 324) / 18, cc = (i % 324) % 18;
            int gy = by0 - 1 + r, gx = bx0 - 1 + cc;
            float v = 0.f;
            if (gy >= 0 && gy < H_ && gx >= 0 && gx < W_)
                v = x[((n*C_ + c0 + cb)*H_ + gy)*W_ + gx];
            win[i] = v;
        }
        __syncthreads();
        #pragma unroll
        for (int cb = 0; cb < 2; cb++) {
            int c = c0 + cb;
            #pragma unroll
            for (int k = 0; k < 9; k++) {
                int ky = k / 3, kx = k % 3;
                float v = win[cb*324 + (ly + ky)*18 + lx + kx];
                h0 += v * whf[(0*C_ + c)*9 + k];
                h1 += v * whf[(1*C_ + c)*9 + k];
                h2 += v * whf[(2*C_ + c)*9 + k];
            }
        }
    }
    h0 += b_head[0]; h1 += b_head[1]; h2 += b_head[2];

    int gy = by0 + ly, gx = bx0 + lx;
    int pix = n*HW_ + gy*W_ + gx;
    g_dx[pix]   = 0.25f * tanhf(h0);
    g_dy[pix]   = 0.25f * tanhf(h1);
    g_mask[pix] = 1.f / (1.f + expf(-h2));
}

// ---------------- kernel 3: deformable sampling + GEMM ----------------
// grid: N*144 blocks (8x8 px tiles), 256 threads: thread=(o=tid&127, pgrp=tid>>7)
// Inner GEMM uses packed f32x2 FFMA2 on pixel pairs.
__global__ __launch_bounds__(256, 2) void k_dcn(const float* __restrict__ x,
                                                float* __restrict__ out) {
    __shared__ float win[CB_*WINSZ_];
    __shared__ __align__(16) float samp[CB_][9][64];
    __shared__ short  bidx[9*64];        // [k][p]
    __shared__ __align__(16) float4 wgt[9*64];  // [k][p]
    __shared__ float red_s[256];
    __shared__ float red_q[256];

    int tid = threadIdx.x;
    int bx  = blockIdx.x;
    int n    = bx / NTILES_;
    int tile = bx % NTILES_;
    int ty0 = (tile / TPI_) * TILE_;
    int tx0 = (tile % TPI_) * TILE_;
    int wy0 = ty0 - 2, wx0 = tx0 - 2;

    // ---- per-block precompute: bilinear corner base + weights (mask folded) ----
    if (tid < 64) {
        int p = tid;
        int ly = p >> 3, lx = p & 7;
        int gy = ty0 + ly, gx = tx0 + lx;
        int pix = n*HW_ + gy*W_ + gx;
        float dx = g_dx[pix], dy = g_dy[pix], m = g_mask[pix];
        const float syc[9] = {0,0,0, 1,0,-1, 1,1,-1};
        const float sxc[9] = {0,1,-1, 0,0,0, 1,-1,1};
        #pragma unroll
        for (int k = 0; k < 9; k++) {
            int ky = k / 3, kx = k % 3;
            float py = (float)(gy + ky - 1) + syc[k]*dx;
            float px = (float)(gx + kx - 1) + sxc[k]*dy;
            float fy0 = floorf(py), fx0 = floorf(px);
            int y0 = (int)fy0, x0 = (int)fx0;
            float fy = py - fy0, fx = px - fx0;
            float v00 = (y0   >= 0 && y0   < H_ && x0   >= 0 && x0   < W_) ? 1.f : 0.f;
            float v01 = (y0   >= 0 && y0   < H_ && x0+1 >= 0 && x0+1 < W_) ? 1.f : 0.f;
            float v10 = (y0+1 >= 0 && y0+1 < H_ && x0   >= 0 && x0   < W_) ? 1.f : 0.f;
            float v11 = (y0+1 >= 0 && y0+1 < H_ && x0+1 >= 0 && x0+1 < W_) ? 1.f : 0.f;
            float4 w4;
            w4.x = (1.f-fy)*(1.f-fx)*v00*m;
            w4.y = (1.f-fy)*fx      *v01*m;
            w4.z = fy      *(1.f-fx)*v10*m;
            w4.w = fy      *fx      *v11*m;
            int ly0 = min(max(y0 - wy0, 0), 10);
            int lx0 = min(max(x0 - wx0, 0), 10);
            bidx[k*64 + p] = (short)(ly0*12 + lx0);
            wgt[k*64 + p]  = w4;
        }
    }

    unsigned long long acc2[16];
    #pragma unroll
    for (int i = 0; i < 16; i++) acc2[i] = 0ull;

    int o   = tid & 127;
    int pb  = (tid >> 7) * 32;
    const float* wTo = g_wT + o;

    int sp = tid & 63;           // sampling: pixel
    int scb = tid >> 6;          // sampling: channel within batch

    for (int c0 = 0; c0 < C_; c0 += CB_) {
        // --- preload weights for CB channels (latency overlaps barriers/sampling)
        float wv[CB_*9];
        const float* wbase = wTo + (c0*9)*COUT_;
        #pragma unroll
        for (int u = 0; u < CB_*9; u++) wv[u] = wbase[u*COUT_];

        __syncthreads();   // prev GEMM done reading samp; win free; (iter0: precompute visible)
        // --- window load: CB 12x12 planes
        #pragma unroll
        for (int i = tid; i < CB_*WINSZ_; i += 256) {
            int cb = i / WINSZ_;
            int r  = (i % WINSZ_) / 12, cc = (i % WINSZ_) % 12;
            int gy = wy0 + r, gx = wx0 + cc;
            float v = 0.f;
            if (gy >= 0 && gy < H_ && gx >= 0 && gx < W_)
                v = x[((n*C_ + c0 + cb)*H_ + gy)*W_ + gx];
            win[i] = v;
        }
        __syncthreads();
        // --- sampling: each thread one (cb, p), loop k
        {
            const float* wp = &win[scb*WINSZ_];
            #pragma unroll
            for (int k = 0; k < 9; k++) {
                int base = bidx[k*64 + sp];
                float4 w4 = wgt[k*64 + sp];
                samp[scb][k][sp] = w4.x*wp[base]    + w4.y*wp[base+1]
                                 + w4.z*wp[base+12] + w4.w*wp[base+13];
            }
        }
        __syncthreads();
        // --- GEMM: acc[p] += w[o,c,k] * samp[cb][k][p], packed pixel pairs
        #pragma unroll
        for (int cb = 0; cb < CB_; cb++) {
            #pragma unroll
            for (int k = 0; k < 9; k++) {
                unsigned long long wv2 = bcast2(wv[cb*9 + k]);
                const ulonglong2* s2 = (const ulonglong2*)(&samp[cb][k][pb]);
                #pragma unroll
                for (int j = 0; j < 8; j++) {
                    ulonglong2 v = s2[j];
                    acc2[2*j]   = ffma2(wv2, v.x, acc2[2*j]);
                    acc2[2*j+1] = ffma2(wv2, v.y, acc2[2*j+1]);
                }
            }
        }
    }

    // ---- write y + deterministic per-block GN partials ----
    float ls = 0.f, lq = 0.f;
    #pragma unroll
    for (int i = 0; i < 16; i++) {
        float a = lo2(acc2[i]);
        float b = hi2(acc2[i]);
        int p0 = pb + 2*i;
        int ly = p0 >> 3, lx = p0 & 7;      // p0 even -> same row as p0+1
        int gy = ty0 + ly, gx = tx0 + lx;
        long idx = ((long)(n*COUT_ + o)*H_ + gy)*W_ + gx;
        out[idx]     = a;
        out[idx + 1] = b;
        ls += a + b; lq += a*a + b*b;
    }
    red_s[tid] = ls; red_q[tid] = lq;
    __syncthreads();
    if (tid < 8) {  // tid = group id; sum the 16 o-channels x 2 pixel-groups
        float s = 0.f, q = 0.f;
        #pragma unroll
        for (int grp = 0; grp < 2; grp++)
            for (int j = 0; j < 16; j++) {
                int t = grp*128 + tid*16 + j;
                s += red_s[t]; q += red_q[t];
            }
        int base = (((n*GN_GROUPS_ + tid)*NTILES_) + tile)*2;
        g_part[base + 0] = s;
        g_part[base + 1] = q;
    }
}

// ---------------- kernel 4: GN stats reduce ----------------
__global__ void k_gnreduce() {
    int t = threadIdx.x;
    if (t < N_*GN_GROUPS_) {
        float s = 0.f, q = 0.f;
        for (int i = 0; i < NTILES_; i++) {
            s += g_part[(t*NTILES_ + i)*2 + 0];
            q += g_part[(t*NTILES_ + i)*2 + 1];
        }
        float inv = 1.f / CNT_PER_GROUP_;
        float mean = s * inv;
        float var  = q * inv - mean*mean;
        g_stats[t*2 + 0] = mean;
        g_stats[t*2 + 1] = rsqrtf(var + GN_EPS_);
    }
}

// ---------------- kernel 5: normalize + affine + relu ----------------
__global__ void k_apply(float* __restrict__ out,
                        const float* __restrict__ gamma,
                        const float* __restrict__ beta) {
    int i = blockIdx.x * 256 + threadIdx.x;
    if (i >= N_*COUT_*HW_) return;
    int c = (i / HW_) % COUT_;
    int n = i / (HW_*COUT_);
    int g = c >> 4;
    float mean = g_stats[(n*GN_GROUPS_ + g)*2 + 0];
    float rstd = g_stats[(n*GN_GROUPS_ + g)*2 + 1];
    float v = (out[i] - mean) * rstd * gamma[c] + beta[c];
    out[i] = fmaxf(v, 0.f);
}

extern "C" void kernel_launch(void* const* d_in, const int* in_sizes, int n_in,
                              void* d_out, int out_size) {
    const float* x       = (const float*)d_in[0];
    const float* w_head  = (const float*)d_in[1];
    const float* b_head  = (const float*)d_in[2];
    const float* w_dcn   = (const float*)d_in[3];
    const float* gamma   = (const float*)d_in[4];
    const float* beta    = (const float*)d_in[5];
    float* out = (float*)d_out;

    k_transpose<<<(CK_*COUT_ + 255)/256, 256>>>(w_dcn);
    k_head<<<N_*36, 256>>>(x, w_head, b_head);
    k_dcn<<<N_*NTILES_, 256>>>(x, out);
    k_gnreduce<<<1, 32>>>();
    k_apply<<<(N_*COUT_*HW_ + 255)/256, 256>>>(out, gamma, beta);
}

// round 7
// speedup vs baseline: 3.7104x; 2.7045x over previous
#include <cuda_runtime.h>
#include <math.h>
#include <stdint.h>

#define N_ 4
#define C_ 128
#define COUT_ 128
#define H_ 96
#define W_ 96
#define HW_ (H_*W_)
#define GN_GROUPS_ 8
#define GN_EPS_ 1e-5f
#define CNT_PER_GROUP_ (16.0f*HW_)

// dcn region: 8 rows x 16 cols of pixels (N=128), M=128, K=1152
#define TILEH_ 8
#define TILEW_ 16
#define NREG_ 72            // (96/8)*(96/16)
#define WR_ 12
#define WC_ 20
#define WPLANE_ 240
#define SSTR_ 136           // samp row stride (conflict-free B-frag LDS)

// dynamic smem map (bytes)
#define SM_BIDX  0          // 9*128*2 = 2304
#define SM_WGT   2304       // 9*128*16 = 18432
#define SM_RED   20736      // 2*32 floats = 256  (+pad)
#define SM_WIN   21248      // 32*240*4 = 30720
#define SM_SAMP  51968      // 32*136*4 = 17408
#define SM_ASM   69376      // 16384 (16B aligned)
#define SM_TOT   85760

// ---------------- scratch ----------------
__device__ float    g_dx[N_*HW_];
__device__ float    g_dy[N_*HW_];
__device__ float    g_mask[N_*HW_];
__device__ uint4    g_wA[144*256];               // A-fragment-ordered tf32 weights (590KB)
__device__ float    g_part[N_*GN_GROUPS_*NREG_*2];
__device__ float    g_stats[N_*GN_GROUPS_*2];

// ---------------- helpers ----------------
__device__ __forceinline__ uint32_t f2tf32(float f) {
    uint32_t u;
    asm("cvt.rna.tf32.f32 %0, %1;" : "=r"(u) : "f"(f));
    return u;
}
__device__ __forceinline__ void mma816(float* d, uint32_t a0, uint32_t a1,
                                       uint32_t a2, uint32_t a3,
                                       uint32_t b0, uint32_t b1) {
    asm volatile("mma.sync.aligned.m16n8k8.row.col.f32.tf32.tf32.f32 "
                 "{%0,%1,%2,%3}, {%4,%5,%6,%7}, {%8,%9}, {%0,%1,%2,%3};"
                 : "+f"(d[0]), "+f"(d[1]), "+f"(d[2]), "+f"(d[3])
                 : "r"(a0), "r"(a1), "r"(a2), "r"(a3), "r"(b0), "r"(b1));
}

// ---------------- kernel 1: weight prep -> A-fragment order (tf32) ----------------
// t = ((q*2 + wm)*4 + mt)*32 + lane, q = ((cg*9)+k)*4+sub
__global__ void k_wprep(const float* __restrict__ w) {
    int t = blockIdx.x * 256 + threadIdx.x;
    if (t >= 144*256) return;
    int lane = t & 31;
    int mt = (t >> 5) & 3;
    int wm = (t >> 7) & 1;
    int q  = t >> 8;
    int sub = q & 3;
    int kk  = (q >> 2) % 9;
    int cg  = q / 36;
    int g = lane >> 2, tg = lane & 3;
    int o = wm*64 + mt*16 + g;
    int c = cg*32 + sub*8 + tg;
    uint4 u;
    u.x = f2tf32(w[o*1152 + c*9 + kk]);
    u.y = f2tf32(w[(o+8)*1152 + c*9 + kk]);
    u.z = f2tf32(w[o*1152 + (c+4)*9 + kk]);
    u.w = f2tf32(w[(o+8)*1152 + (c+4)*9 + kk]);
    g_wA[t] = u;
}

// ---------------- kernel 2: head conv + activations (4 ch/iter) ----------------
__global__ __launch_bounds__(256) void k_head(const float* __restrict__ x,
                                              const float* __restrict__ w_head,
                                              const float* __restrict__ b_head) {
    __shared__ float whf[3*C_*9];
    __shared__ float win[4*18*18];

    int tid = threadIdx.x;
    int bx  = blockIdx.x;
    int n   = bx / 36;
    int t   = bx % 36;
    int by0 = (t / 6) * 16;
    int bx0 = (t % 6) * 16;

    for (int i = tid; i < 3*C_*9; i += 256) whf[i] = w_head[i];

    int ly = tid / 16, lx = tid % 16;
    float h0 = 0.f, h1 = 0.f, h2 = 0.f;

    for (int c0 = 0; c0 < C_; c0 += 4) {
        __syncthreads();
        for (int i = tid; i < 4*324; i += 256) {
            int cb = i / 324;
            int r  = (i % 324) / 18, cc = (i % 324) % 18;
            int gy = by0 - 1 + r, gx = bx0 - 1 + cc;
            float v = 0.f;
            if (gy >= 0 && gy < H_ && gx >= 0 && gx < W_)
                v = x[((n*C_ + c0 + cb)*H_ + gy)*W_ + gx];
            win[i] = v;
        }
        __syncthreads();
        #pragma unroll
        for (int cb = 0; cb < 4; cb++) {
            int c = c0 + cb;
            #pragma unroll
            for (int k = 0; k < 9; k++) {
                int ky = k / 3, kx = k % 3;
                float v = win[cb*324 + (ly + ky)*18 + lx + kx];
                h0 += v * whf[(0*C_ + c)*9 + k];
                h1 += v * whf[(1*C_ + c)*9 + k];
                h2 += v * whf[(2*C_ + c)*9 + k];
            }
        }
    }
    h0 += b_head[0]; h1 += b_head[1]; h2 += b_head[2];

    int gy = by0 + ly, gx = bx0 + lx;
    int pix = n*HW_ + gy*W_ + gx;
    g_dx[pix]   = 0.25f * tanhf(h0);
    g_dy[pix]   = 0.25f * tanhf(h1);
    g_mask[pix] = 1.f / (1.f + expf(-h2));
}

// ---------------- kernel 3: deformable sampling + tf32 warp-MMA GEMM ----------------
// grid: N*72 blocks, 256 threads (8 warps = 2 M-halves x 4 N-quarters)
__global__ __launch_bounds__(256, 2) void k_dcn(const float* __restrict__ x,
                                                float* __restrict__ out) {
    extern __shared__ char smem[];
    short*  bidx = (short*)(smem + SM_BIDX);
    float4* wgt  = (float4*)(smem + SM_WGT);
    float*  red  = (float*)(smem + SM_RED);      // [w][mt] x2
    float*  win  = (float*)(smem + SM_WIN);
    float*  samp = (float*)(smem + SM_SAMP);     // [c][SSTR_] tf32 bits as float
    float4* Asm  = (float4*)(smem + SM_ASM);     // A frags, 1024 float4

    int tid = threadIdx.x, w = tid >> 5, lane = tid & 31;
    int g = lane >> 2, tg = lane & 3;
    int wm = w >> 2, ng = w & 3;
    int n0w = ng * 32;
    int bx = blockIdx.x;
    int n   = bx / NREG_;
    int reg = bx % NREG_;
    int ty0 = (reg / 6) * TILEH_;
    int tx0 = (reg % 6) * TILEW_;
    int wy0 = ty0 - 2, wx0 = tx0 - 2;

    // ---- bilinear tables: 128 px x 9 taps (mask folded) ----
    if (tid < 128) {
        int p  = tid;
        int ly = p >> 4, lx = p & 15;
        int gy = ty0 + ly, gx = tx0 + lx;
        int pix = n*HW_ + gy*W_ + gx;
        float dx = g_dx[pix], dy = g_dy[pix], m = g_mask[pix];
        const float syc[9] = {0,0,0, 1,0,-1, 1,1,-1};
        const float sxc[9] = {0,1,-1, 0,0,0, 1,-1,1};
        #pragma unroll
        for (int k = 0; k < 9; k++) {
            int ky = k / 3, kx = k % 3;
            float py = (float)(gy + ky - 1) + syc[k]*dx;
            float px = (float)(gx + kx - 1) + sxc[k]*dy;
            float fy0 = floorf(py), fx0 = floorf(px);
            int y0 = (int)fy0, x0 = (int)fx0;
            float fy = py - fy0, fx = px - fx0;
            float v00 = (y0   >= 0 && y0   < H_ && x0   >= 0 && x0   < W_) ? 1.f : 0.f;
            float v01 = (y0   >= 0 && y0   < H_ && x0+1 >= 0 && x0+1 < W_) ? 1.f : 0.f;
            float v10 = (y0+1 >= 0 && y0+1 < H_ && x0   >= 0 && x0   < W_) ? 1.f : 0.f;
            float v11 = (y0+1 >= 0 && y0+1 < H_ && x0+1 >= 0 && x0+1 < W_) ? 1.f : 0.f;
            float4 w4;
            w4.x = (1.f-fy)*(1.f-fx)*v00*m;
            w4.y = (1.f-fy)*fx      *v01*m;
            w4.z = fy      *(1.f-fx)*v10*m;
            w4.w = fy      *fx      *v11*m;
            int ly0 = min(max(y0 - wy0, 0), WR_-2);
            int lx0 = min(max(x0 - wx0, 0), WC_-2);
            bidx[k*128 + p] = (short)(ly0*WC_ + lx0);
            wgt[k*128 + p]  = w4;
        }
    }

    float acc[4][4][4];
    #pragma unroll
    for (int a = 0; a < 4; a++)
        #pragma unroll
        for (int b = 0; b < 4; b++)
            #pragma unroll
            for (int r = 0; r < 4; r++) acc[a][b][r] = 0.f;

    int sp  = tid & 127;                // sampling pixel
    int sc0 = (tid >> 7) * 16;          // sampling channel half

    for (int cg = 0; cg < 4; cg++) {
        __syncthreads();                // win free
        for (int i = tid; i < 32*WPLANE_; i += 256) {
            int c = i / WPLANE_;
            int r = (i % WPLANE_) / WC_, cc = (i % WPLANE_) % WC_;
            int gy = wy0 + r, gx = wx0 + cc;
            float v = 0.f;
            if (gy >= 0 && gy < H_ && gx >= 0 && gx < W_)
                v = x[((n*C_ + cg*32 + c)*H_ + gy)*W_ + gx];
            win[i] = v;
        }
        __syncthreads();

        for (int k = 0; k < 9; k++) {
            // ---- produce B (sampled, tf32) + stage A frags ----
            {
                int base = bidx[k*128 + sp];
                float4 w4 = wgt[k*128 + sp];
                #pragma unroll
                for (int j = 0; j < 16; j++) {
                    int c = sc0 + j;
                    const float* wc = win + c*WPLANE_ + base;
                    float s = w4.x*wc[0] + w4.y*wc[1] + w4.z*wc[WC_] + w4.w*wc[WC_+1];
                    samp[c*SSTR_ + sp] = __uint_as_float(f2tf32(s));
                }
                const uint4* asrc = g_wA + (cg*9 + k)*1024;
                float4* adst = Asm;
                #pragma unroll
                for (int i = 0; i < 4; i++) {
                    uint4 u = asrc[tid + i*256];
                    adst[tid + i*256] = make_float4(__uint_as_float(u.x), __uint_as_float(u.y),
                                                    __uint_as_float(u.z), __uint_as_float(u.w));
                }
            }
            __syncthreads();
            // ---- MMA phase: 4 sub-chunks of 8 channels ----
            #pragma unroll
            for (int sub = 0; sub < 4; sub++) {
                float4 a[4];
                #pragma unroll
                for (int mt = 0; mt < 4; mt++)
                    a[mt] = Asm[sub*256 + wm*128 + mt*32 + lane];
                uint32_t b0[4], b1[4];
                #pragma unroll
                for (int nt = 0; nt < 4; nt++) {
                    int px = n0w + nt*8 + g;
                    b0[nt] = __float_as_uint(samp[(sub*8 + tg)*SSTR_ + px]);
                    b1[nt] = __float_as_uint(samp[(sub*8 + tg + 4)*SSTR_ + px]);
                }
                #pragma unroll
                for (int mt = 0; mt < 4; mt++)
                    #pragma unroll
                    for (int nt = 0; nt < 4; nt++)
                        mma816(acc[mt][nt],
                               __float_as_uint(a[mt].x), __float_as_uint(a[mt].y),
                               __float_as_uint(a[mt].z), __float_as_uint(a[mt].w),
                               b0[nt], b1[nt]);
            }
            __syncthreads();
        }
    }

    // ---- epilogue: stores + GN partials ----
    float s4[4] = {0,0,0,0}, q4[4] = {0,0,0,0};
    #pragma unroll
    for (int mt = 0; mt < 4; mt++) {
        int o1 = wm*64 + mt*16 + g;
        #pragma unroll
        for (int nt = 0; nt < 4; nt++) {
            int p  = n0w + nt*8 + 2*tg;
            int gy = ty0 + (p >> 4), gx = tx0 + (p & 15);
            float2 lo = make_float2(acc[mt][nt][0], acc[mt][nt][1]);
            float2 hi = make_float2(acc[mt][nt][2], acc[mt][nt][3]);
            *(float2*)&out[((n*COUT_ + o1    )*H_ + gy)*W_ + gx] = lo;
            *(float2*)&out[((n*COUT_ + o1 + 8)*H_ + gy)*W_ + gx] = hi;
            #pragma unroll
            for (int r = 0; r < 4; r++) {
                float v = acc[mt][nt][r];
                s4[mt] += v; q4[mt] += v*v;
            }
        }
    }
    #pragma unroll
    for (int mt = 0; mt < 4; mt++) {
        #pragma unroll
        for (int o = 16; o; o >>= 1) {
            s4[mt] += __shfl_xor_sync(0xFFFFFFFFu, s4[mt], o);
            q4[mt] += __shfl_xor_sync(0xFFFFFFFFu, q4[mt], o);
        }
    }
    if (lane == 0) {
        #pragma unroll
        for (int mt = 0; mt < 4; mt++) {
            red[w*4 + mt]      = s4[mt];
            red[32 + w*4 + mt] = q4[mt];
        }
    }
    __syncthreads();
    if (tid < 8) {                    // group gid = wm*4+mt
        int gwm = tid >> 2, gmt = tid & 3;
        float s = 0.f, q = 0.f;
        #pragma unroll
        for (int j = 0; j < 4; j++) { // over ng
            s += red[(gwm*4 + j)*4 + gmt];
            q += red[32 + (gwm*4 + j)*4 + gmt];
        }
        int base = (((n*GN_GROUPS_ + tid)*NREG_) + reg)*2;
        g_part[base + 0] = s;
        g_part[base + 1] = q;
    }
}

// ---------------- kernel 4: GN stats reduce ----------------
__global__ void k_gnreduce(void) {
    int b = blockIdx.x;
    int lane = threadIdx.x;
    float s = 0.f, q = 0.f;
    for (int i = lane; i < NREG_; i += 32) {
        s += g_part[(b*NREG_ + i)*2 + 0];
        q += g_part[(b*NREG_ + i)*2 + 1];
    }
    #pragma unroll
    for (int o = 16; o; o >>= 1) {
        s += __shfl_xor_sync(0xFFFFFFFFu, s, o);
        q += __shfl_xor_sync(0xFFFFFFFFu, q, o);
    }
    if (lane == 0) {
        float inv = 1.f / CNT_PER_GROUP_;
        float mean = s * inv;
        float var  = q * inv - mean*mean;
        g_stats[b*2 + 0] = mean;
        g_stats[b*2 + 1] = rsqrtf(var + GN_EPS_);
    }
}

// ---------------- kernel 5: normalize + affine + relu (float4) ----------------
__global__ void k_apply(float* __restrict__ out,
                        const float* __restrict__ gamma,
                        const float* __restrict__ beta) {
    int i4 = blockIdx.x * 256 + threadIdx.x;
    if (i4 >= N_*COUT_*HW_/4) return;
    int i = i4 * 4;
    int c = (i / HW_) % COUT_;
    int n = i / (HW_*COUT_);
    int g = c >> 4;
    float mean = g_stats[(n*GN_GROUPS_ + g)*2 + 0];
    float rstd = g_stats[(n*GN_GROUPS_ + g)*2 + 1];
    float sc = rstd * gamma[c];
    float sh = beta[c] - mean * sc;
    float4 v = ((float4*)out)[i4];
    v.x = fmaxf(v.x*sc + sh, 0.f);
    v.y = fmaxf(v.y*sc + sh, 0.f);
    v.z = fmaxf(v.z*sc + sh, 0.f);
    v.w = fmaxf(v.w*sc + sh, 0.f);
    ((float4*)out)[i4] = v;
}

extern "C" void kernel_launch(void* const* d_in, const int* in_sizes, int n_in,
                              void* d_out, int out_size) {
    const float* x       = (const float*)d_in[0];
    const float* w_head  = (const float*)d_in[1];
    const float* b_head  = (const float*)d_in[2];
    const float* w_dcn   = (const float*)d_in[3];
    const float* gamma   = (const float*)d_in[4];
    const float* beta    = (const float*)d_in[5];
    float* out = (float*)d_out;

    cudaFuncSetAttribute(k_dcn, cudaFuncAttributeMaxDynamicSharedMemorySize, SM_TOT);

    k_wprep<<<144, 256>>>(w_dcn);
    k_head<<<N_*36, 256>>>(x, w_head, b_head);
    k_dcn<<<N_*NREG_, 256, SM_TOT>>>(x, out);
    k_gnreduce<<<N_*GN_GROUPS_, 32>>>();
    k_apply<<<(N_*COUT_*HW_/4 + 255)/256, 256>>>(out, gamma, beta);
}

// round 9
// speedup vs baseline: 5.1564x; 1.3897x over previous
#include <cuda_runtime.h>
#include <cuda_fp16.h>
#include <math.h>
#include <stdint.h>

#define N_ 4
#define C_ 128
#define COUT_ 128
#define H_ 96
#define W_ 96
#define HW_ (H_*W_)
#define GN_GROUPS_ 8
#define GN_EPS_ 1e-5f
#define CNT_PER_GROUP_ (16.0f*HW_)

// dcn region: 8 rows x 16 cols of pixels (N=128), M=128, K=1152
#define TILEH_ 8
#define TILEW_ 16
#define NREG_ 72            // (96/8)*(96/16)
#define WR_ 12
#define WC_ 20
#define WWORDS_ 240         // WR_*WC_ half2 words per channel
#define SROW_ 21            // samp row stride in uint32 words (42 halves)

// dynamic smem map (bytes) for k_dcn
#define SM_BIDX  0          // 9*128*2 = 2304
#define SM_WGT   2304       // 9*128*16 = 18432 -> 20736
#define SM_RED   20736      // 256 -> 20992
#define SM_WIN2  20992      // 32*240*4 = 30720 -> 51712
#define SM_SAMP  51712      // 128*21*4 = 10752 -> 62464
#define SM_ASM   62464      // 8192 -> 70656
#define SM_TOT   70656

// ---------------- scratch ----------------
__device__ float    g_dx[N_*HW_];
__device__ float    g_dy[N_*HW_];
__device__ float    g_mask[N_*HW_];
__device__ uint4    g_wA[36*512];                // A-fragment-ordered fp16 weights (294KB)
__device__ float    g_part[N_*GN_GROUPS_*NREG_*2];
__device__ float    g_stats[N_*GN_GROUPS_*2];

// ---------------- helpers ----------------
__device__ __forceinline__ void mma16816(float* d, uint32_t a0, uint32_t a1,
                                         uint32_t a2, uint32_t a3,
                                         uint32_t b0, uint32_t b1) {
    asm volatile("mma.sync.aligned.m16n8k16.row.col.f32.f16.f16.f32 "
                 "{%0,%1,%2,%3}, {%4,%5,%6,%7}, {%8,%9}, {%0,%1,%2,%3};"
                 : "+f"(d[0]), "+f"(d[1]), "+f"(d[2]), "+f"(d[3])
                 : "r"(a0), "r"(a1), "r"(a2), "r"(a3), "r"(b0), "r"(b1));
}
__device__ __forceinline__ uint32_t packh2(float a, float b) {
    __half2 h = __floats2half2_rn(a, b);
    return *(uint32_t*)&h;
}

// ---------------- kernel 1: head conv + weight prep (merged) ----------------
// blocks [0,144): head conv 16x16 tiles; blocks [144,216): A-fragment weight prep
__global__ __launch_bounds__(256) void k_prep(const float* __restrict__ x,
                                              const float* __restrict__ w_head,
                                              const float* __restrict__ b_head,
                                              const float* __restrict__ w_dcn) {
    __shared__ float4 whf4[C_*9];     // [c][k] -> (w0,w1,w2,0)
    __shared__ float  win[8*324];

    int tid = threadIdx.x;
    int bx  = blockIdx.x;

    if (bx >= 144) {
        // ---- weight prep: t indexes [ci][sub][wm][mt][lane] ----
        int t = (bx - 144) * 256 + tid;     // 0..18431
        int lane = t & 31;
        int mt  = (t >> 5) & 3;
        int wm  = (t >> 7) & 1;
        int sub = (t >> 8) & 1;
        int ci  = t >> 9;                   // 0..35
        int cg = ci / 9, kk = ci % 9;
        int g = lane >> 2, tg = lane & 3;
        int o  = wm*64 + mt*16 + g;
        int c0 = cg*32 + sub*16 + 2*tg;
        uint4 u;
        u.x = packh2(w_dcn[o*1152 + c0*9 + kk],       w_dcn[o*1152 + (c0+1)*9 + kk]);
        u.y = packh2(w_dcn[(o+8)*1152 + c0*9 + kk],   w_dcn[(o+8)*1152 + (c0+1)*9 + kk]);
        u.z = packh2(w_dcn[o*1152 + (c0+8)*9 + kk],   w_dcn[o*1152 + (c0+9)*9 + kk]);
        u.w = packh2(w_dcn[(o+8)*1152 + (c0+8)*9 + kk], w_dcn[(o+8)*1152 + (c0+9)*9 + kk]);
        g_wA[t] = u;
        return;
    }

    // ---- head conv ----
    int n   = bx / 36;
    int t   = bx % 36;
    int by0 = (t / 6) * 16;
    int bx0 = (t % 6) * 16;

    for (int i = tid; i < C_*9; i += 256) {
        int c = i / 9, k = i % 9;
        whf4[i] = make_float4(w_head[(0*C_ + c)*9 + k],
                              w_head[(1*C_ + c)*9 + k],
                              w_head[(2*C_ + c)*9 + k], 0.f);
    }

    int ly = tid / 16, lx = tid % 16;
    float h0 = 0.f, h1 = 0.f, h2 = 0.f;

    for (int c0 = 0; c0 < C_; c0 += 8) {
        __syncthreads();
        for (int i = tid; i < 8*324; i += 256) {
            int cb = i / 324;
            int r  = (i % 324) / 18, cc = (i % 324) % 18;
            int gy = by0 - 1 + r, gx = bx0 - 1 + cc;
            float v = 0.f;
            if (gy >= 0 && gy < H_ && gx >= 0 && gx < W_)
                v = x[((n*C_ + c0 + cb)*H_ + gy)*W_ + gx];
            win[i] = v;
        }
        __syncthreads();
        #pragma unroll
        for (int cb = 0; cb < 8; cb++) {
            int c = c0 + cb;
            #pragma unroll
            for (int k = 0; k < 9; k++) {
                int ky = k / 3, kx = k % 3;
                float v = win[cb*324 + (ly + ky)*18 + lx + kx];
                float4 wv = whf4[c*9 + k];
                h0 += v * wv.x;
                h1 += v * wv.y;
                h2 += v * wv.z;
            }
        }
    }
    h0 += b_head[0]; h1 += b_head[1]; h2 += b_head[2];

    int gy = by0 + ly, gx = bx0 + lx;
    int pix = n*HW_ + gy*W_ + gx;
    g_dx[pix]   = 0.25f * tanhf(h0);
    g_dy[pix]   = 0.25f * tanhf(h1);
    g_mask[pix] = 1.f / (1.f + expf(-h2));
}

// ---------------- kernel 2: deformable sampling + fp16 warp-MMA GEMM ----------------
// grid: N*72 blocks, 256 threads (8 warps = 2 M-halves x 4 N-quarters)
__global__ __launch_bounds__(256, 2) void k_dcn(const float* __restrict__ x,
                                                float* __restrict__ out) {
    extern __shared__ char smem[];
    short*    bidx  = (short*)(smem + SM_BIDX);
    float4*   wgt   = (float4*)(smem + SM_WGT);
    float*    red   = (float*)(smem + SM_RED);
    __half2*  win2  = (__half2*)(smem + SM_WIN2);   // [c][r*20+x] = (v[x], v[x+1])
    uint32_t* sampW = (uint32_t*)(smem + SM_SAMP);  // [px][SROW_] words (half2 pairs of channels)
    uint4*    AsmU  = (uint4*)(smem + SM_ASM);      // A frags, 512 uint4

    int tid = threadIdx.x, w = tid >> 5, lane = tid & 31;
    int g = lane >> 2, tg = lane & 3;
    int wm = w >> 2, ng = w & 3;
    int n0w = ng * 32;
    int bx = blockIdx.x;
    int n   = bx / NREG_;
    int reg = bx % NREG_;
    int ty0 = (reg / 6) * TILEH_;
    int tx0 = (reg % 6) * TILEW_;
    int wy0 = ty0 - 2, wx0 = tx0 - 2;

    // ---- bilinear tables: 128 px x 9 taps (mask folded) ----
    if (tid < 128) {
        int p  = tid;
        int ly = p >> 4, lx = p & 15;
        int gy = ty0 + ly, gx = tx0 + lx;
        int pix = n*HW_ + gy*W_ + gx;
        float dx = g_dx[pix], dy = g_dy[pix], m = g_mask[pix];
        const float syc[9] = {0,0,0, 1,0,-1, 1,1,-1};
        const float sxc[9] = {0,1,-1, 0,0,0, 1,-1,1};
        #pragma unroll
        for (int k = 0; k < 9; k++) {
            int ky = k / 3, kx = k % 3;
            float py = (float)(gy + ky - 1) + syc[k]*dx;
            float px = (float)(gx + kx - 1) + sxc[k]*dy;
            float fy0 = floorf(py), fx0 = floorf(px);
            int y0 = (int)fy0, x0 = (int)fx0;
            float fy = py - fy0, fx = px - fx0;
            float v00 = (y0   >= 0 && y0   < H_ && x0   >= 0 && x0   < W_) ? 1.f : 0.f;
            float v01 = (y0   >= 0 && y0   < H_ && x0+1 >= 0 && x0+1 < W_) ? 1.f : 0.f;
            float v10 = (y0+1 >= 0 && y0+1 < H_ && x0   >= 0 && x0   < W_) ? 1.f : 0.f;
            float v11 = (y0+1 >= 0 && y0+1 < H_ && x0+1 >= 0 && x0+1 < W_) ? 1.f : 0.f;
            float4 w4;
            w4.x = (1.f-fy)*(1.f-fx)*v00*m;
            w4.y = (1.f-fy)*fx      *v01*m;
            w4.z = fy      *(1.f-fx)*v10*m;
            w4.w = fy      *fx      *v11*m;
            int ly0 = min(max(y0 - wy0, 0), WR_-2);
            int lx0 = min(max(x0 - wx0, 0), WC_-2);
            bidx[k*128 + p] = (short)(ly0*WC_ + lx0);
            wgt[k*128 + p]  = w4;
        }
    }

    float acc[4][4][4];
    #pragma unroll
    for (int a = 0; a < 4; a++)
        #pragma unroll
        for (int b = 0; b < 4; b++)
            #pragma unroll
            for (int r = 0; r < 4; r++) acc[a][b][r] = 0.f;

    int sp  = tid & 127;                // sampling pixel
    int sc0 = (tid >> 7) * 16;          // sampling channel half (0 or 16)

    for (int cg = 0; cg < 4; cg++) {
        // win2 safe to overwrite: previous tap's post-MMA barrier passed.
        // (first iter: tables written above, barrier below covers them)
        for (int i = tid; i < 32*WWORDS_; i += 256) {
            int c = i / WWORDS_;
            int rem = i % WWORDS_;
            int r = rem / WC_, xx = rem % WC_;
            int gy = wy0 + r, gx = wx0 + xx;
            float v0 = 0.f, v1 = 0.f;
            if (gy >= 0 && gy < H_) {
                const float* row = x + ((n*C_ + cg*32 + c)*H_ + gy)*W_;
                if (gx >= 0 && gx < W_)       v0 = row[gx];
                if (gx+1 >= 0 && gx+1 < W_)   v1 = row[gx+1];
            }
            win2[i] = __floats2half2_rn(v0, v1);
        }
        __syncthreads();

        for (int k = 0; k < 9; k++) {
            int ci = cg*9 + k;
            // ---- prefetch A frags into regs (overlaps sampling) ----
            const uint4* asrc = g_wA + ci*512;
            uint4 ar0 = asrc[tid];
            uint4 ar1 = asrc[tid + 256];

            // ---- sampling -> samp (fp16 pairs) ----
            {
                int base = bidx[k*128 + sp];
                float4 w4 = wgt[k*128 + sp];
                #pragma unroll
                for (int j = 0; j < 16; j += 2) {
                    int c = sc0 + j;
                    float2 a0 = __half22float2(win2[c*WWORDS_ + base]);
                    float2 a1 = __half22float2(win2[c*WWORDS_ + base + WC_]);
                    float s0 = w4.x*a0.x + w4.y*a0.y + w4.z*a1.x + w4.w*a1.y;
                    float2 b0f = __half22float2(win2[(c+1)*WWORDS_ + base]);
                    float2 b1f = __half22float2(win2[(c+1)*WWORDS_ + base + WC_]);
                    float s1 = w4.x*b0f.x + w4.y*b0f.y + w4.z*b1f.x + w4.w*b1f.y;
                    sampW[sp*SROW_ + (c >> 1)] = packh2(s0, s1);
                }
            }
            // ---- stage A frags ----
            AsmU[tid]       = ar0;
            AsmU[tid + 256] = ar1;
            __syncthreads();

            // ---- MMA phase: 2 sub-chunks of 16 channels ----
            #pragma unroll
            for (int sub = 0; sub < 2; sub++) {
                uint4 a[4];
                #pragma unroll
                for (int mt = 0; mt < 4; mt++)
                    a[mt] = AsmU[sub*256 + wm*128 + mt*32 + lane];
                uint32_t b0[4], b1[4];
                #pragma unroll
                for (int nt = 0; nt < 4; nt++) {
                    int px = n0w + nt*8 + g;
                    b0[nt] = sampW[px*SROW_ + sub*8 + tg];
                    b1[nt] = sampW[px*SROW_ + sub*8 + tg + 4];
                }
                #pragma unroll
                for (int mt = 0; mt < 4; mt++)
                    #pragma unroll
                    for (int nt = 0; nt < 4; nt++)
                        mma16816(acc[mt][nt], a[mt].x, a[mt].y, a[mt].z, a[mt].w,
                                 b0[nt], b1[nt]);
            }
            __syncthreads();
        }
    }

    // ---- epilogue: stores + GN partials ----
    float s4[4] = {0,0,0,0}, q4[4] = {0,0,0,0};
    #pragma unroll
    for (int mt = 0; mt < 4; mt++) {
        int o1 = wm*64 + mt*16 + g;
        #pragma unroll
        for (int nt = 0; nt < 4; nt++) {
            int p  = n0w + nt*8 + 2*tg;
            int gy = ty0 + (p >> 4), gx = tx0 + (p & 15);
            float2 lo = make_float2(acc[mt][nt][0], acc[mt][nt][1]);
            float2 hi = make_float2(acc[mt][nt][2], acc[mt][nt][3]);
            *(float2*)&out[((n*COUT_ + o1    )*H_ + gy)*W_ + gx] = lo;
            *(float2*)&out[((n*COUT_ + o1 + 8)*H_ + gy)*W_ + gx] = hi;
            #pragma unroll
            for (int r = 0; r < 4; r++) {
                float v = acc[mt][nt][r];
                s4[mt] += v; q4[mt] += v*v;
            }
        }
    }
    #pragma unroll
    for (int mt = 0; mt < 4; mt++) {
        #pragma unroll
        for (int o = 16; o; o >>= 1) {
            s4[mt] += __shfl_xor_sync(0xFFFFFFFFu, s4[mt], o);
            q4[mt] += __shfl_xor_sync(0xFFFFFFFFu, q4[mt], o);
        }
    }
    if (lane == 0) {
        #pragma unroll
        for (int mt = 0; mt < 4; mt++) {
            red[w*4 + mt]      = s4[mt];
            red[32 + w*4 + mt] = q4[mt];
        }
    }
    __syncthreads();
    if (tid < 8) {                    // group gid = wm*4+mt
        int gwm = tid >> 2, gmt = tid & 3;
        float s = 0.f, q = 0.f;
        #pragma unroll
        for (int j = 0; j < 4; j++) {
            s += red[(gwm*4 + j)*4 + gmt];
            q += red[32 + (gwm*4 + j)*4 + gmt];
        }
        int base = (((n*GN_GROUPS_ + tid)*NREG_) + reg)*2;
        g_part[base + 0] = s;
        g_part[base + 1] = q;
    }
}

// ---------------- kernel 3: GN stats reduce ----------------
__global__ void k_gnreduce(void) {
    int b = blockIdx.x;
    int lane = threadIdx.x;
    float s = 0.f, q = 0.f;
    for (int i = lane; i < NREG_; i += 32) {
        s += g_part[(b*NREG_ + i)*2 + 0];
        q += g_part[(b*NREG_ + i)*2 + 1];
    }
    #pragma unroll
    for (int o = 16; o; o >>= 1) {
        s += __shfl_xor_sync(0xFFFFFFFFu, s, o);
        q += __shfl_xor_sync(0xFFFFFFFFu, q, o);
    }
    if (lane == 0) {
        float inv = 1.f / CNT_PER_GROUP_;
        float mean = s * inv;
        float var  = q * inv - mean*mean;
        g_stats[b*2 + 0] = mean;
        g_stats[b*2 + 1] = rsqrtf(var + GN_EPS_);
    }
}

// ---------------- kernel 4: normalize + affine + relu (float4) ----------------
__global__ void k_apply(float* __restrict__ out,
                        const float* __restrict__ gamma,
                        const float* __restrict__ beta) {
    int i4 = blockIdx.x * 256 + threadIdx.x;
    if (i4 >= N_*COUT_*HW_/4) return;
    int i = i4 * 4;
    int c = (i / HW_) % COUT_;
    int n = i / (HW_*COUT_);
    int g = c >> 4;
    float mean = g_stats[(n*GN_GROUPS_ + g)*2 + 0];
    float rstd = g_stats[(n*GN_GROUPS_ + g)*2 + 1];
    float sc = rstd * gamma[c];
    float sh = beta[c] - mean * sc;
    float4 v = ((float4*)out)[i4];
    v.x = fmaxf(v.x*sc + sh, 0.f);
    v.y = fmaxf(v.y*sc + sh, 0.f);
    v.z = fmaxf(v.z*sc + sh, 0.f);
    v.w = fmaxf(v.w*sc + sh, 0.f);
    ((float4*)out)[i4] = v;
}

extern "C" void kernel_launch(void* const* d_in, const int* in_sizes, int n_in,
                              void* d_out, int out_size) {
    const float* x       = (const float*)d_in[0];
    const float* w_head  = (const float*)d_in[1];
    const float* b_head  = (const float*)d_in[2];
    const float* w_dcn   = (const float*)d_in[3];
    const float* gamma   = (const float*)d_in[4];
    const float* beta    = (const float*)d_in[5];
    float* out = (float*)d_out;

    cudaFuncSetAttribute(k_dcn, cudaFuncAttributeMaxDynamicSharedMemorySize, SM_TOT);

    k_prep<<<216, 256>>>(x, w_head, b_head, w_dcn);
    k_dcn<<<N_*NREG_, 256, SM_TOT>>>(x, out);
    k_gnreduce<<<N_*GN_GROUPS_, 32>>>();
    k_apply<<<(N_*COUT_*HW_/4 + 255)/256, 256>>>(out, gamma, beta);
}